// round 16
// baseline (speedup 1.0000x reference)
#include <cuda_runtime.h>
#include <cuda_fp16.h>
#include <cstdint>

#define N_NODES 50000
#define N_EDGES 800000
#define D_IN    256
#define D_HID   256
#define D_OUT   128
#define HISTB   3125           // ceil(800000/256)
#define YSPB    12500
#define NTILES  391            // ceil(50000/128)
#define GGRID   148

// ---------------- scratch ------------------------------------------------------
__device__ __half g_H1[(size_t)N_NODES * D_HID];
__device__ __half g_H2[(size_t)N_NODES * D_HID];
__device__ __half g_H3[(size_t)N_NODES * D_OUT];
__device__ __half g_Yh[(size_t)N_NODES * D_IN];
__device__ __half g_W1T[D_HID * D_IN];
__device__ __half g_W2T[D_OUT * D_HID];
__device__ int   g_rowptr[N_NODES + 1];
__device__ int   g_cursor[N_NODES];
__device__ int   g_bsum[256];
__device__ int2  g_ecv[N_EDGES];

// stream/events created at static-init (before harness mem checkpoints);
// intentionally never destroyed (2 harness calls total).
struct StreamCtx {
    cudaStream_t s2;
    cudaEvent_t e0, eCSR, eLo, eHi, eG2;
    StreamCtx() {
        cudaStreamCreateWithFlags(&s2, cudaStreamNonBlocking);
        cudaEventCreateWithFlags(&e0,   cudaEventDisableTiming);
        cudaEventCreateWithFlags(&eCSR, cudaEventDisableTiming);
        cudaEventCreateWithFlags(&eLo,  cudaEventDisableTiming);
        cudaEventCreateWithFlags(&eHi,  cudaEventDisableTiming);
        cudaEventCreateWithFlags(&eG2,  cudaEventDisableTiming);
    }
};
static StreamCtx g_ctx;

// ---------------- init: W transposes (fp16) + Y convert (NO hist) ---------------
__global__ void k_initYW(const float* __restrict__ W1,
                         const float* __restrict__ W2,
                         const float* __restrict__ Y) {
    int b = blockIdx.x;
    if (b < 256) {               // W1 [256][256] -> T fp16
        int i = b * 256 + threadIdx.x;
        int r = i >> 8, c = i & 255;
        g_W1T[(size_t)c * D_IN + r] = __float2half(W1[i]);
        return;
    }
    b -= 256;
    if (b < 128) {               // W2 [256][128] -> T fp16
        int i = b * 256 + threadIdx.x;
        int r = i >> 7, c = i & 127;
        g_W2T[(size_t)c * D_HID + r] = __float2half(W2[i]);
        return;
    }
    b -= 128;
    {                            // Y convert
        int j = b * 256 + threadIdx.x;
        float4 f = __ldg(((const float4*)Y) + j);
        uint2 h;
        __half2 h01 = __floats2half2_rn(f.x, f.y);
        __half2 h23 = __floats2half2_rn(f.z, f.w);
        h.x = *(uint32_t*)&h01; h.y = *(uint32_t*)&h23;
        ((uint2*)g_Yh)[j] = h;
    }
}

__global__ void k_hist(const int* __restrict__ erow) {
    int i = blockIdx.x * 256 + threadIdx.x;
    if (i < N_EDGES) atomicAdd(&g_rowptr[erow[i] + 1], 1);
}

// ---------------- parallel scan (2 phases) --------------------------------------
__global__ void k_scan1() {
    __shared__ int sh[256];
    int t = threadIdx.x;
    int idx = blockIdx.x * 256 + t;
    int v = (idx < N_NODES + 1) ? g_rowptr[idx] : 0;
    sh[t] = v;
    __syncthreads();
#pragma unroll
    for (int off = 1; off < 256; off <<= 1) {
        int u = (t >= off) ? sh[t - off] : 0;
        __syncthreads();
        sh[t] += u;
        __syncthreads();
    }
    if (idx < N_NODES + 1) g_rowptr[idx] = sh[t];
    if (t == 255) g_bsum[blockIdx.x] = sh[255];
}

__global__ void k_scan3() {
    __shared__ int sh[256];
    int t = threadIdx.x;
    sh[t] = (t < (int)blockIdx.x) ? g_bsum[t] : 0;
    __syncthreads();
#pragma unroll
    for (int off = 128; off > 0; off >>= 1) {
        if (t < off) sh[t] += sh[t + off];
        __syncthreads();
    }
    int offset = sh[0];
    int idx = blockIdx.x * 256 + t;
    if (idx < N_NODES + 1) {
        int v = g_rowptr[idx] + offset;
        g_rowptr[idx] = v;
        if (idx < N_NODES) g_cursor[idx] = v;
    }
}

__global__ void k_scatter(const int* __restrict__ erow, const int* __restrict__ ecol,
                          const float* __restrict__ eval) {
    int i = blockIdx.x * 256 + threadIdx.x;
    if (i < N_EDGES) {
        int r = erow[i];
        int p = atomicAdd(&g_cursor[r], 1);
        g_ecv[p] = make_int2(ecol[i], __float_as_int(eval[i]));
    }
}

// ---------------- PTX helpers ----------------------------------------------------
__device__ __forceinline__ void mma_f16(float* c, const uint32_t* a, const uint32_t* b) {
    asm("mma.sync.aligned.m16n8k16.row.col.f32.f16.f16.f32 "
        "{%0,%1,%2,%3}, {%4,%5,%6,%7}, {%8,%9}, {%0,%1,%2,%3};"
        : "+f"(c[0]), "+f"(c[1]), "+f"(c[2]), "+f"(c[3])
        : "r"(a[0]), "r"(a[1]), "r"(a[2]), "r"(a[3]), "r"(b[0]), "r"(b[1]));
}

#define LDSM4(r0, r1, r2, r3, addr)                                            \
    asm volatile("ldmatrix.sync.aligned.m8n8.x4.shared.b16 {%0,%1,%2,%3}, [%4];" \
                 : "=r"(r0), "=r"(r1), "=r"(r2), "=r"(r3) : "r"(addr))
#define CPA16(dst, src, n)                                                     \
    asm volatile("cp.async.cg.shared.global [%0], [%1], 16, %2;"               \
                 :: "r"(dst), "l"(src), "r"(n))
#define CP_COMMIT() asm volatile("cp.async.commit_group;" ::: "memory")
#define CP_WAIT0()  asm volatile("cp.async.wait_group 0;" ::: "memory")

#define SWZ(r, c) ((uint32_t)((r) * 64 + (((c) ^ (((r) >> 1) & 3)) * 16)))

#define B1SLAB 16384
#define ASLAB  8192
#define A1OFF  131072
#define DSM1   (A1OFF + 8 * ASLAB)   // 196608
#define B2SLAB 8192
#define A2OFF  32768
#define DSM2H  (A2OFF + 4 * ASLAB)   // 65536

// ---------------- GEMM1: resident W1 + full-A smem -------------------------------
__global__ __launch_bounds__(512, 1)
void k_gemm1()
{
    extern __shared__ __align__(128) char dsm[];
    uint32_t bB = (uint32_t)(uint64_t)__cvta_generic_to_shared(dsm);
    uint32_t bA = bB + A1OFF;
    int tid = threadIdx.x, lane = tid & 31, wid = tid >> 5;
    int wm = (wid & 3) * 32;
    int wn = (wid >> 2) * 64;

#pragma unroll
    for (int it = 0; it < 16; it++) {
        int ch = tid + it * 512;
        int s = ch >> 10, w = ch & 1023;
        int r = w >> 2, c = w & 3;
        CPA16(bB + (uint32_t)s * B1SLAB + SWZ(r, c),
              g_W1T + (size_t)r * 256 + s * 32 + c * 8, 16);
    }
    CP_COMMIT();

    uint32_t aRow[2], aS[2], bRow[4], bS[4];
    uint32_t kaBase = (lane & 16) ? 16u : 0u;
    uint32_t kbBase = (lane & 8) ? 16u : 0u;
    {
        int ra = (lane & 7) + ((lane & 8) ? 8 : 0);
#pragma unroll
        for (int mi = 0; mi < 2; mi++) {
            int r = wm + mi * 16 + ra;
            aRow[mi] = (uint32_t)(r * 64);
            aS[mi]   = (uint32_t)(((r >> 1) & 3) * 16);
        }
        int rb = (lane & 7) + ((lane & 16) ? 8 : 0);
#pragma unroll
        for (int p = 0; p < 4; p++) {
            int r = wn + p * 16 + rb;
            bRow[p] = (uint32_t)(r * 64);
            bS[p]   = (uint32_t)(((r >> 1) & 3) * 16);
        }
    }

    for (int my = blockIdx.x; my < NTILES; my += GGRID) {
        int rowBase = my * 128;
        __syncthreads();
        {
            int r = tid >> 2, c = tid & 3;
            int gr = rowBase + r;
            int ok = (gr < N_NODES) ? 16 : 0;
            int grc = (gr < N_NODES) ? gr : (N_NODES - 1);
            const __half* src = g_Yh + (size_t)grc * 256 + c * 8;
            uint32_t dst = bA + SWZ(r, c);
#pragma unroll
            for (int s = 0; s < 8; s++)
                CPA16(dst + (uint32_t)s * ASLAB, src + s * 32, ok);
        }
        CP_COMMIT();
        CP_WAIT0();
        __syncthreads();

        float acc[2][8][4];
#pragma unroll
        for (int mi = 0; mi < 2; mi++)
#pragma unroll
            for (int ni = 0; ni < 8; ni++)
#pragma unroll
                for (int q = 0; q < 4; q++) acc[mi][ni][q] = 0.f;

#pragma unroll
        for (int kt = 0; kt < 8; kt++) {
            uint32_t curA = bA + (uint32_t)kt * ASLAB;
            uint32_t curB = bB + (uint32_t)kt * B1SLAB;
#pragma unroll
            for (int ks = 0; ks < 2; ks++) {
                uint32_t kA = (uint32_t)(ks * 32) + kaBase;
                uint32_t kB = (uint32_t)(ks * 32) + kbBase;
                uint32_t af[2][4], bf[4][4];
#pragma unroll
                for (int p = 0; p < 4; p++)
                    LDSM4(bf[p][0], bf[p][1], bf[p][2], bf[p][3],
                          curB + bRow[p] + (kB ^ bS[p]));
#pragma unroll
                for (int mi = 0; mi < 2; mi++)
                    LDSM4(af[mi][0], af[mi][1], af[mi][2], af[mi][3],
                          curA + aRow[mi] + (kA ^ aS[mi]));
#pragma unroll
                for (int mi = 0; mi < 2; mi++)
#pragma unroll
                    for (int p = 0; p < 4; p++) {
                        mma_f16(acc[mi][p * 2],     af[mi], &bf[p][0]);
                        mma_f16(acc[mi][p * 2 + 1], af[mi], &bf[p][2]);
                    }
            }
        }

#pragma unroll
        for (int mi = 0; mi < 2; mi++) {
            int rr = rowBase + wm + mi * 16 + (lane >> 2);
#pragma unroll
            for (int ni = 0; ni < 8; ni++) {
                int cc = wn + ni * 8 + (lane & 3) * 2;
                if (rr < N_NODES)
                    *(__half2*)&g_H1[(size_t)rr * 256 + cc] =
                        __floats2half2_rn(acc[mi][ni][0], acc[mi][ni][1]);
                if (rr + 8 < N_NODES)
                    *(__half2*)&g_H1[(size_t)(rr + 8) * 256 + cc] =
                        __floats2half2_rn(acc[mi][ni][2], acc[mi][ni][3]);
            }
        }
    }
}

// ---------------- GEMM2 K-half: resident W2-half + A-half smem -------------------
template <bool ACC>
__global__ __launch_bounds__(512, 1)
void k_gemm2h(int kh)
{
    extern __shared__ __align__(128) char dsm[];
    uint32_t bB = (uint32_t)(uint64_t)__cvta_generic_to_shared(dsm);
    uint32_t bA = bB + A2OFF;
    int tid = threadIdx.x, lane = tid & 31, wid = tid >> 5;
    int wm = (wid & 3) * 32;
    int wn = (wid >> 2) * 32;
    int kOff = kh * 128;

    // load W2 K-half resident (4 slabs x 8KB)
#pragma unroll
    for (int s = 0; s < 4; s++) {
        int r = tid >> 2, c = tid & 3;
        CPA16(bB + (uint32_t)s * B2SLAB + SWZ(r, c),
              g_W2T + (size_t)r * 256 + kOff + s * 32 + c * 8, 16);
    }
    CP_COMMIT();

    uint32_t aRow[2], aS[2], bRow[2], bS[2];
    uint32_t kaBase = (lane & 16) ? 16u : 0u;
    uint32_t kbBase = (lane & 8) ? 16u : 0u;
    {
        int ra = (lane & 7) + ((lane & 8) ? 8 : 0);
#pragma unroll
        for (int mi = 0; mi < 2; mi++) {
            int r = wm + mi * 16 + ra;
            aRow[mi] = (uint32_t)(r * 64);
            aS[mi]   = (uint32_t)(((r >> 1) & 3) * 16);
        }
        int rb = (lane & 7) + ((lane & 16) ? 8 : 0);
#pragma unroll
        for (int p = 0; p < 2; p++) {
            int r = wn + p * 16 + rb;
            bRow[p] = (uint32_t)(r * 64);
            bS[p]   = (uint32_t)(((r >> 1) & 3) * 16);
        }
    }

    for (int my = blockIdx.x; my < NTILES; my += GGRID) {
        int rowBase = my * 128;
        __syncthreads();
        {
            int r = tid >> 2, c = tid & 3;
            int gr = rowBase + r;
            int ok = (gr < N_NODES) ? 16 : 0;
            int grc = (gr < N_NODES) ? gr : (N_NODES - 1);
            const __half* src = g_H2 + (size_t)grc * 256 + kOff + c * 8;
            uint32_t dst = bA + SWZ(r, c);
#pragma unroll
            for (int s = 0; s < 4; s++)
                CPA16(dst + (uint32_t)s * ASLAB, src + s * 32, ok);
        }
        CP_COMMIT();
        CP_WAIT0();
        __syncthreads();

        float acc[2][4][4];
#pragma unroll
        for (int mi = 0; mi < 2; mi++)
#pragma unroll
            for (int ni = 0; ni < 4; ni++)
#pragma unroll
                for (int q = 0; q < 4; q++) acc[mi][ni][q] = 0.f;

#pragma unroll
        for (int kt = 0; kt < 4; kt++) {
            uint32_t curA = bA + (uint32_t)kt * ASLAB;
            uint32_t curB = bB + (uint32_t)kt * B2SLAB;
#pragma unroll
            for (int ks = 0; ks < 2; ks++) {
                uint32_t kA = (uint32_t)(ks * 32) + kaBase;
                uint32_t kB = (uint32_t)(ks * 32) + kbBase;
                uint32_t af[2][4], bf[2][4];
#pragma unroll
                for (int p = 0; p < 2; p++)
                    LDSM4(bf[p][0], bf[p][1], bf[p][2], bf[p][3],
                          curB + bRow[p] + (kB ^ bS[p]));
#pragma unroll
                for (int mi = 0; mi < 2; mi++)
                    LDSM4(af[mi][0], af[mi][1], af[mi][2], af[mi][3],
                          curA + aRow[mi] + (kA ^ aS[mi]));
#pragma unroll
                for (int mi = 0; mi < 2; mi++)
#pragma unroll
                    for (int p = 0; p < 2; p++) {
                        mma_f16(acc[mi][p * 2],     af[mi], &bf[p][0]);
                        mma_f16(acc[mi][p * 2 + 1], af[mi], &bf[p][2]);
                    }
            }
        }

#pragma unroll
        for (int mi = 0; mi < 2; mi++) {
            int rr = rowBase + wm + mi * 16 + (lane >> 2);
#pragma unroll
            for (int ni = 0; ni < 4; ni++) {
                int cc = wn + ni * 8 + (lane & 3) * 2;
                if (rr < N_NODES) {
                    __half2* p = (__half2*)&g_H3[(size_t)rr * 128 + cc];
                    float2 v = make_float2(acc[mi][ni][0], acc[mi][ni][1]);
                    if (ACC) { float2 o = __half22float2(*p); v.x += o.x; v.y += o.y; }
                    *p = __floats2half2_rn(v.x, v.y);
                }
                if (rr + 8 < N_NODES) {
                    __half2* p = (__half2*)&g_H3[(size_t)(rr + 8) * 128 + cc];
                    float2 v = make_float2(acc[mi][ni][2], acc[mi][ni][3]);
                    if (ACC) { float2 o = __half22float2(*p); v.x += o.x; v.y += o.y; }
                    *p = __floats2half2_rn(v.x, v.y);
                }
            }
        }
    }
}

// fp16 gather helper
__device__ __forceinline__ void fma_h4(float4& acc, float v, uint2 raw) {
    float2 a01 = __half22float2(*(__half2*)&raw.x);
    float2 a23 = __half22float2(*(__half2*)&raw.y);
    acc.x += v * a01.x; acc.y += v * a01.y;
    acc.z += v * a23.x; acc.w += v * a23.y;
}

// ---------------- SpMM1 feature-half: H2[:,foff:foff+128] --------------------------
__global__ void k_spmm1h(int foff) {
    int r = blockIdx.x * 8 + threadIdx.y;
    if (r >= N_NODES) return;
    int f4 = foff + threadIdx.x * 4;        // 32 lanes x 4 feats = 128
    int e   = g_rowptr[r];
    int end = g_rowptr[r + 1];
    float4 acc = make_float4(0.f, 0.f, 0.f, 0.f);
    for (; e + 4 <= end; e += 4) {
        int2 cv0 = __ldg(&g_ecv[e]);
        int2 cv1 = __ldg(&g_ecv[e + 1]);
        int2 cv2 = __ldg(&g_ecv[e + 2]);
        int2 cv3 = __ldg(&g_ecv[e + 3]);
        uint2 x0 = __ldg((const uint2*)&g_H1[(size_t)cv0.x * D_HID + f4]);
        uint2 x1 = __ldg((const uint2*)&g_H1[(size_t)cv1.x * D_HID + f4]);
        uint2 x2 = __ldg((const uint2*)&g_H1[(size_t)cv2.x * D_HID + f4]);
        uint2 x3 = __ldg((const uint2*)&g_H1[(size_t)cv3.x * D_HID + f4]);
        fma_h4(acc, __int_as_float(cv0.y), x0);
        fma_h4(acc, __int_as_float(cv1.y), x1);
        fma_h4(acc, __int_as_float(cv2.y), x2);
        fma_h4(acc, __int_as_float(cv3.y), x3);
    }
    for (; e < end; e++) {
        int2 cv = __ldg(&g_ecv[e]);
        uint2 x = __ldg((const uint2*)&g_H1[(size_t)cv.x * D_HID + f4]);
        fma_h4(acc, __int_as_float(cv.y), x);
    }
    acc.x = fmaxf(acc.x, 0.f); acc.y = fmaxf(acc.y, 0.f);
    acc.z = fmaxf(acc.z, 0.f); acc.w = fmaxf(acc.w, 0.f);
    uint2 h;
    __half2 h01 = __floats2half2_rn(acc.x, acc.y);
    __half2 h23 = __floats2half2_rn(acc.z, acc.w);
    h.x = *(uint32_t*)&h01; h.y = *(uint32_t*)&h23;
    *(uint2*)&g_H2[(size_t)r * D_HID + f4] = h;
}

// ---------------- SpMM2 ------------------------------------------------------------
__global__ void k_spmm2(float* __restrict__ out) {
    int r = blockIdx.x * 8 + threadIdx.y;
    if (r >= N_NODES) return;
    int f4 = threadIdx.x * 4;
    int e   = g_rowptr[r];
    int end = g_rowptr[r + 1];
    float4 acc = make_float4(0.f, 0.f, 0.f, 0.f);
    for (; e + 4 <= end; e += 4) {
        int2 cv0 = __ldg(&g_ecv[e]);
        int2 cv1 = __ldg(&g_ecv[e + 1]);
        int2 cv2 = __ldg(&g_ecv[e + 2]);
        int2 cv3 = __ldg(&g_ecv[e + 3]);
        uint2 x0 = __ldg((const uint2*)&g_H3[(size_t)cv0.x * D_OUT + f4]);
        uint2 x1 = __ldg((const uint2*)&g_H3[(size_t)cv1.x * D_OUT + f4]);
        uint2 x2 = __ldg((const uint2*)&g_H3[(size_t)cv2.x * D_OUT + f4]);
        uint2 x3 = __ldg((const uint2*)&g_H3[(size_t)cv3.x * D_OUT + f4]);
        fma_h4(acc, __int_as_float(cv0.y), x0);
        fma_h4(acc, __int_as_float(cv1.y), x1);
        fma_h4(acc, __int_as_float(cv2.y), x2);
        fma_h4(acc, __int_as_float(cv3.y), x3);
    }
    for (; e < end; e++) {
        int2 cv = __ldg(&g_ecv[e]);
        uint2 x = __ldg((const uint2*)&g_H3[(size_t)cv.x * D_OUT + f4]);
        fma_h4(acc, __int_as_float(cv.y), x);
    }
    *(float4*)&out[(size_t)r * D_OUT + f4] = acc;
}

// ---------------- launch -----------------------------------------------------------
extern "C" void kernel_launch(void* const* d_in, const int* in_sizes, int n_in,
                              void* d_out, int out_size) {
    const float* Y        = (const float*)d_in[0];
    const int*   edge_row = (const int*)d_in[1];
    const int*   edge_col = (const int*)d_in[2];
    const float* edge_val = (const float*)d_in[3];
    const float* W1       = (const float*)d_in[4];
    const float* W2       = (const float*)d_in[5];
    float*       out      = (float*)d_out;

    int *pRowptr;
    cudaGetSymbolAddress((void**)&pRowptr, g_rowptr);

    cudaFuncSetAttribute(k_gemm1, cudaFuncAttributeMaxDynamicSharedMemorySize, DSM1);
    cudaFuncSetAttribute(k_gemm2h<false>, cudaFuncAttributeMaxDynamicSharedMemorySize, DSM2H);
    cudaFuncSetAttribute(k_gemm2h<true>,  cudaFuncAttributeMaxDynamicSharedMemorySize, DSM2H);

    cudaStream_t s2 = g_ctx.s2;

    // fork: CSR chain on side stream
    cudaEventRecord(g_ctx.e0, 0);
    cudaStreamWaitEvent(s2, g_ctx.e0, 0);
    cudaMemsetAsync(pRowptr, 0, (N_NODES + 1) * sizeof(int), s2);
    k_hist<<<HISTB, 256, 0, s2>>>(edge_row);
    k_scan1<<<196, 256, 0, s2>>>();
    k_scan3<<<196, 256, 0, s2>>>();
    k_scatter<<<HISTB, 256, 0, s2>>>(edge_row, edge_col, edge_val);
    cudaEventRecord(g_ctx.eCSR, s2);

    // main stream: dense chain
    k_initYW<<<256 + 128 + YSPB, 256>>>(W1, W2, Y);
    k_gemm1<<<GGRID, 512, DSM1>>>();
    cudaStreamWaitEvent(0, g_ctx.eCSR, 0);

    dim3 sblk(32, 8);
    k_spmm1h<<<(N_NODES + 7) / 8, sblk>>>(0);
    cudaEventRecord(g_ctx.eLo, 0);
    k_spmm1h<<<(N_NODES + 7) / 8, sblk>>>(128);
    cudaEventRecord(g_ctx.eHi, 0);

    // GEMM2 K-halves pipelined on side stream
    cudaStreamWaitEvent(s2, g_ctx.eLo, 0);
    k_gemm2h<false><<<GGRID, 512, DSM2H, s2>>>(0);
    cudaStreamWaitEvent(s2, g_ctx.eHi, 0);
    k_gemm2h<true><<<GGRID, 512, DSM2H, s2>>>(1);
    cudaEventRecord(g_ctx.eG2, s2);

    cudaStreamWaitEvent(0, g_ctx.eG2, 0);
    k_spmm2<<<(N_NODES + 7) / 8, sblk>>>(out);
}

// round 17
// speedup vs baseline: 1.2895x; 1.2895x over previous
#include <cuda_runtime.h>
#include <cuda_fp16.h>
#include <cstdint>

#define N_NODES 50000
#define N_EDGES 800000
#define D_IN    256
#define D_HID   256
#define D_OUT   128
#define HISTB   3125           // ceil(800000/256)
#define YSPB    12500          // 50000*256/4 float4 / 256 threads
#define NTILES  391            // ceil(50000/128)
#define GGRID   148            // persistent GEMM blocks (1/SM)

// ---------------- scratch ------------------------------------------------------
__device__ __half g_H1[(size_t)N_NODES * D_HID];
__device__ __half g_H2[(size_t)N_NODES * D_HID];
__device__ __half g_H3[(size_t)N_NODES * D_OUT];
__device__ __half g_Yh[(size_t)N_NODES * D_IN];
__device__ __half g_W1T[D_HID * D_IN];
__device__ __half g_W2T[D_OUT * D_HID];
__device__ int   g_rowptr[N_NODES + 1];
__device__ int   g_cursor[N_NODES];
__device__ int   g_bsum[256];
__device__ int2  g_ecv[N_EDGES];

// ---------------- K1: hist + W transposes (fp16) + Y convert -------------------
__global__ void k_init_all(const int* __restrict__ erow,
                           const float* __restrict__ W1,
                           const float* __restrict__ W2,
                           const float* __restrict__ Y) {
    int b = blockIdx.x;
    if (b < HISTB) {
        int i = b * 256 + threadIdx.x;
        if (i < N_EDGES) atomicAdd(&g_rowptr[erow[i] + 1], 1);
        return;
    }
    b -= HISTB;
    if (b < 256) {               // W1 [256][256] -> T fp16
        int i = b * 256 + threadIdx.x;
        int r = i >> 8, c = i & 255;
        g_W1T[(size_t)c * D_IN + r] = __float2half(W1[i]);
        return;
    }
    b -= 256;
    if (b < 128) {               // W2 [256][128] -> T fp16
        int i = b * 256 + threadIdx.x;
        int r = i >> 7, c = i & 127;
        g_W2T[(size_t)c * D_HID + r] = __float2half(W2[i]);
        return;
    }
    b -= 128;
    {                            // Y convert: 3.2M float4 chunks -> 4x fp16
        int j = b * 256 + threadIdx.x;
        float4 f = __ldg(((const float4*)Y) + j);
        uint2 h;
        __half2 h01 = __floats2half2_rn(f.x, f.y);
        __half2 h23 = __floats2half2_rn(f.z, f.w);
        h.x = *(uint32_t*)&h01; h.y = *(uint32_t*)&h23;
        ((uint2*)g_Yh)[j] = h;
    }
}

// ---------------- parallel scan (2 phases) --------------------------------------
__global__ void k_scan1() {
    __shared__ int sh[256];
    int t = threadIdx.x;
    int idx = blockIdx.x * 256 + t;
    int v = (idx < N_NODES + 1) ? g_rowptr[idx] : 0;
    sh[t] = v;
    __syncthreads();
#pragma unroll
    for (int off = 1; off < 256; off <<= 1) {
        int u = (t >= off) ? sh[t - off] : 0;
        __syncthreads();
        sh[t] += u;
        __syncthreads();
    }
    if (idx < N_NODES + 1) g_rowptr[idx] = sh[t];
    if (t == 255) g_bsum[blockIdx.x] = sh[255];
}

__global__ void k_scan3() {
    __shared__ int sh[256];
    int t = threadIdx.x;
    sh[t] = (t < (int)blockIdx.x) ? g_bsum[t] : 0;
    __syncthreads();
#pragma unroll
    for (int off = 128; off > 0; off >>= 1) {
        if (t < off) sh[t] += sh[t + off];
        __syncthreads();
    }
    int offset = sh[0];
    int idx = blockIdx.x * 256 + t;
    if (idx < N_NODES + 1) {
        int v = g_rowptr[idx] + offset;
        g_rowptr[idx] = v;
        if (idx < N_NODES) g_cursor[idx] = v;
    }
}

// ---------------- PTX helpers ----------------------------------------------------
__device__ __forceinline__ void mma_f16(float* c, const uint32_t* a, const uint32_t* b) {
    asm("mma.sync.aligned.m16n8k16.row.col.f32.f16.f16.f32 "
        "{%0,%1,%2,%3}, {%4,%5,%6,%7}, {%8,%9}, {%0,%1,%2,%3};"
        : "+f"(c[0]), "+f"(c[1]), "+f"(c[2]), "+f"(c[3])
        : "r"(a[0]), "r"(a[1]), "r"(a[2]), "r"(a[3]), "r"(b[0]), "r"(b[1]));
}

#define LDSM4(r0, r1, r2, r3, addr)                                            \
    asm volatile("ldmatrix.sync.aligned.m8n8.x4.shared.b16 {%0,%1,%2,%3}, [%4];" \
                 : "=r"(r0), "=r"(r1), "=r"(r2), "=r"(r3) : "r"(addr))
#define CPA16(dst, src, n)                                                     \
    asm volatile("cp.async.cg.shared.global [%0], [%1], 16, %2;"               \
                 :: "r"(dst), "l"(src), "r"(n))
#define CP_COMMIT() asm volatile("cp.async.commit_group;" ::: "memory")

#define SWZ(r, c) ((uint32_t)((r) * 64 + (((c) ^ (((r) >> 1) & 3)) * 16)))

#define B1SLAB 16384    // GEMM1: 8 slabs x 16KB resident W1
#define DSM1   163840   // + A ring 4 x 8KB
#define B2SLAB 8192     // GEMM2: 8 slabs x 8KB resident W2
#define DSM2   98304
#define ASTG   8192
#define A1OFF  131072
#define A2OFF  65536

// ---------------- GEMM1 persistent (resident W1) + scatter tail ------------------
__global__ __launch_bounds__(512, 1)
void k_gemm1_scatter(const int* __restrict__ erow, const int* __restrict__ ecol,
                     const float* __restrict__ eval)
{
    extern __shared__ __align__(128) char dsm[];
    uint32_t sb = (uint32_t)(uint64_t)__cvta_generic_to_shared(dsm);
    uint32_t bB = sb, bA = sb + A1OFF;
    int tid = threadIdx.x, lane = tid & 31, wid = tid >> 5;
    int wm = (wid & 3) * 32;
    int wn = (wid >> 2) * 64;

    uint32_t aRow[2], aS[2], bRow[4], bS[4];
    uint32_t kaBase = (lane & 16) ? 16u : 0u;
    uint32_t kbBase = (lane & 8) ? 16u : 0u;
    {
        int ra = (lane & 7) + ((lane & 8) ? 8 : 0);
#pragma unroll
        for (int mi = 0; mi < 2; mi++) {
            int r = wm + mi * 16 + ra;
            aRow[mi] = (uint32_t)(r * 64);
            aS[mi]   = (uint32_t)(((r >> 1) & 3) * 16);
        }
        int rb = (lane & 7) + ((lane & 16) ? 8 : 0);
#pragma unroll
        for (int p = 0; p < 4; p++) {
            int r = wn + p * 16 + rb;
            bRow[p] = (uint32_t)(r * 64);
            bS[p]   = (uint32_t)(((r >> 1) & 3) * 16);
        }
    }

    bool first = true;
    for (int my = blockIdx.x; my < NTILES; my += GGRID) {
        int rowBase = my * 128;
        float acc[2][8][4];
#pragma unroll
        for (int mi = 0; mi < 2; mi++)
#pragma unroll
            for (int ni = 0; ni < 8; ni++)
#pragma unroll
                for (int q = 0; q < 4; q++) acc[mi][ni][q] = 0.f;

#pragma unroll
        for (int s = 0; s < 3; s++) {
            {
                int r = tid >> 2, c = tid & 3;
                int gr = rowBase + r;
                int ok = (gr < N_NODES) ? 16 : 0;
                int grc = (gr < N_NODES) ? gr : (N_NODES - 1);
                CPA16(bA + (uint32_t)s * ASTG + SWZ(r, c),
                      g_Yh + (size_t)grc * 256 + s * 32 + c * 8, ok);
            }
            if (first) {
#pragma unroll
                for (int it = 0; it < 2; it++) {
                    int ch = tid + it * 512;
                    int r = ch >> 2, c = ch & 3;
                    CPA16(bB + (uint32_t)s * B1SLAB + SWZ(r, c),
                          g_W1T + (size_t)r * 256 + s * 32 + c * 8, 16);
                }
            }
            CP_COMMIT();
        }

        for (int kt = 0; kt < 8; kt++) {
            uint32_t curA = bA + (uint32_t)(kt & 3) * ASTG;
            uint32_t curB = bB + (uint32_t)kt * B1SLAB;
            if (kt < 5) {
                int s = kt + 3;
                {
                    int r = tid >> 2, c = tid & 3;
                    int gr = rowBase + r;
                    int ok = (gr < N_NODES) ? 16 : 0;
                    int grc = (gr < N_NODES) ? gr : (N_NODES - 1);
                    CPA16(bA + (uint32_t)(s & 3) * ASTG + SWZ(r, c),
                          g_Yh + (size_t)grc * 256 + s * 32 + c * 8, ok);
                }
                if (first) {
#pragma unroll
                    for (int it = 0; it < 2; it++) {
                        int ch = tid + it * 512;
                        int r = ch >> 2, c = ch & 3;
                        CPA16(bB + (uint32_t)s * B1SLAB + SWZ(r, c),
                              g_W1T + (size_t)r * 256 + s * 32 + c * 8, 16);
                    }
                }
                CP_COMMIT();
                asm volatile("cp.async.wait_group 3;" ::: "memory");
            } else if (kt == 5) {
                asm volatile("cp.async.wait_group 2;" ::: "memory");
            } else if (kt == 6) {
                asm volatile("cp.async.wait_group 1;" ::: "memory");
            } else {
                asm volatile("cp.async.wait_group 0;" ::: "memory");
            }
            __syncthreads();

#pragma unroll
            for (int ks = 0; ks < 2; ks++) {
                uint32_t kA = (uint32_t)(ks * 32) + kaBase;
                uint32_t kB = (uint32_t)(ks * 32) + kbBase;
                uint32_t af[2][4], bf[4][4];
#pragma unroll
                for (int p = 0; p < 4; p++)
                    LDSM4(bf[p][0], bf[p][1], bf[p][2], bf[p][3],
                          curB + bRow[p] + (kB ^ bS[p]));
#pragma unroll
                for (int mi = 0; mi < 2; mi++)
                    LDSM4(af[mi][0], af[mi][1], af[mi][2], af[mi][3],
                          curA + aRow[mi] + (kA ^ aS[mi]));
#pragma unroll
                for (int mi = 0; mi < 2; mi++)
#pragma unroll
                    for (int p = 0; p < 4; p++) {
                        mma_f16(acc[mi][p * 2],     af[mi], &bf[p][0]);
                        mma_f16(acc[mi][p * 2 + 1], af[mi], &bf[p][2]);
                    }
            }
            __syncthreads();
        }

#pragma unroll
        for (int mi = 0; mi < 2; mi++) {
            int rr = rowBase + wm + mi * 16 + (lane >> 2);
#pragma unroll
            for (int ni = 0; ni < 8; ni++) {
                int cc = wn + ni * 8 + (lane & 3) * 2;
                if (rr < N_NODES)
                    *(__half2*)&g_H1[(size_t)rr * 256 + cc] =
                        __floats2half2_rn(acc[mi][ni][0], acc[mi][ni][1]);
                if (rr + 8 < N_NODES)
                    *(__half2*)&g_H1[(size_t)(rr + 8) * 256 + cc] =
                        __floats2half2_rn(acc[mi][ni][2], acc[mi][ni][3]);
            }
        }
        first = false;
    }

    // scatter: grid-stride over edges
    for (int i = blockIdx.x * 512 + tid; i < N_EDGES; i += GGRID * 512) {
        int r = erow[i];
        int p = atomicAdd(&g_cursor[r], 1);
        g_ecv[p] = make_int2(ecol[i], __float_as_int(eval[i]));
    }
}

// ---------------- GEMM2 persistent (resident W2) ---------------------------------
__global__ __launch_bounds__(512, 1)
void k_gemm2()
{
    extern __shared__ __align__(128) char dsm[];
    uint32_t sb = (uint32_t)(uint64_t)__cvta_generic_to_shared(dsm);
    uint32_t bB = sb, bA = sb + A2OFF;
    int tid = threadIdx.x, lane = tid & 31, wid = tid >> 5;
    int wm = (wid & 3) * 32;
    int wn = (wid >> 2) * 32;

    uint32_t aRow[2], aS[2], bRow[2], bS[2];
    uint32_t kaBase = (lane & 16) ? 16u : 0u;
    uint32_t kbBase = (lane & 8) ? 16u : 0u;
    {
        int ra = (lane & 7) + ((lane & 8) ? 8 : 0);
#pragma unroll
        for (int mi = 0; mi < 2; mi++) {
            int r = wm + mi * 16 + ra;
            aRow[mi] = (uint32_t)(r * 64);
            aS[mi]   = (uint32_t)(((r >> 1) & 3) * 16);
        }
        int rb = (lane & 7) + ((lane & 16) ? 8 : 0);
#pragma unroll
        for (int p = 0; p < 2; p++) {
            int r = wn + p * 16 + rb;
            bRow[p] = (uint32_t)(r * 64);
            bS[p]   = (uint32_t)(((r >> 1) & 3) * 16);
        }
    }

    bool first = true;
    for (int my = blockIdx.x; my < NTILES; my += GGRID) {
        int rowBase = my * 128;
        float acc[2][4][4];
#pragma unroll
        for (int mi = 0; mi < 2; mi++)
#pragma unroll
            for (int ni = 0; ni < 4; ni++)
#pragma unroll
                for (int q = 0; q < 4; q++) acc[mi][ni][q] = 0.f;

#pragma unroll
        for (int s = 0; s < 3; s++) {
            {
                int r = tid >> 2, c = tid & 3;
                int gr = rowBase + r;
                int ok = (gr < N_NODES) ? 16 : 0;
                int grc = (gr < N_NODES) ? gr : (N_NODES - 1);
                CPA16(bA + (uint32_t)s * ASTG + SWZ(r, c),
                      g_H2 + (size_t)grc * 256 + s * 32 + c * 8, ok);
            }
            if (first) {
                int r = tid >> 2, c = tid & 3;
                CPA16(bB + (uint32_t)s * B2SLAB + SWZ(r, c),
                      g_W2T + (size_t)r * 256 + s * 32 + c * 8, 16);
            }
            CP_COMMIT();
        }

        for (int kt = 0; kt < 8; kt++) {
            uint32_t curA = bA + (uint32_t)(kt & 3) * ASTG;
            uint32_t curB = bB + (uint32_t)kt * B2SLAB;
            if (kt < 5) {
                int s = kt + 3;
                {
                    int r = tid >> 2, c = tid & 3;
                    int gr = rowBase + r;
                    int ok = (gr < N_NODES) ? 16 : 0;
                    int grc = (gr < N_NODES) ? gr : (N_NODES - 1);
                    CPA16(bA + (uint32_t)(s & 3) * ASTG + SWZ(r, c),
                          g_H2 + (size_t)grc * 256 + s * 32 + c * 8, ok);
                }
                if (first) {
                    int r = tid >> 2, c = tid & 3;
                    CPA16(bB + (uint32_t)s * B2SLAB + SWZ(r, c),
                          g_W2T + (size_t)r * 256 + s * 32 + c * 8, 16);
                }
                CP_COMMIT();
                asm volatile("cp.async.wait_group 3;" ::: "memory");
            } else if (kt == 5) {
                asm volatile("cp.async.wait_group 2;" ::: "memory");
            } else if (kt == 6) {
                asm volatile("cp.async.wait_group 1;" ::: "memory");
            } else {
                asm volatile("cp.async.wait_group 0;" ::: "memory");
            }
            __syncthreads();

#pragma unroll
            for (int ks = 0; ks < 2; ks++) {
                uint32_t kA = (uint32_t)(ks * 32) + kaBase;
                uint32_t kB = (uint32_t)(ks * 32) + kbBase;
                uint32_t af[2][4], bf[2][4];
#pragma unroll
                for (int p = 0; p < 2; p++)
                    LDSM4(bf[p][0], bf[p][1], bf[p][2], bf[p][3],
                          curB + bRow[p] + (kB ^ bS[p]));
#pragma unroll
                for (int mi = 0; mi < 2; mi++)
                    LDSM4(af[mi][0], af[mi][1], af[mi][2], af[mi][3],
                          curA + aRow[mi] + (kA ^ aS[mi]));
#pragma unroll
                for (int mi = 0; mi < 2; mi++)
#pragma unroll
                    for (int p = 0; p < 2; p++) {
                        mma_f16(acc[mi][p * 2],     af[mi], &bf[p][0]);
                        mma_f16(acc[mi][p * 2 + 1], af[mi], &bf[p][2]);
                    }
            }
            __syncthreads();
        }

#pragma unroll
        for (int mi = 0; mi < 2; mi++) {
            int rr = rowBase + wm + mi * 16 + (lane >> 2);
#pragma unroll
            for (int ni = 0; ni < 4; ni++) {
                int cc = wn + ni * 8 + (lane & 3) * 2;
                if (rr < N_NODES)
                    *(__half2*)&g_H3[(size_t)rr * 128 + cc] =
                        __floats2half2_rn(acc[mi][ni][0], acc[mi][ni][1]);
                if (rr + 8 < N_NODES)
                    *(__half2*)&g_H3[(size_t)(rr + 8) * 128 + cc] =
                        __floats2half2_rn(acc[mi][ni][2], acc[mi][ni][3]);
            }
        }
        first = false;
    }
}

// fp16 gather helper: 8 halves (uint4) -> 8 f32 accumulators
__device__ __forceinline__ void fma_h8(float* acc, float v, uint4 raw) {
    float2 a01 = __half22float2(*(__half2*)&raw.x);
    float2 a23 = __half22float2(*(__half2*)&raw.y);
    float2 a45 = __half22float2(*(__half2*)&raw.z);
    float2 a67 = __half22float2(*(__half2*)&raw.w);
    acc[0] += v * a01.x; acc[1] += v * a01.y;
    acc[2] += v * a23.x; acc[3] += v * a23.y;
    acc[4] += v * a45.x; acc[5] += v * a45.y;
    acc[6] += v * a67.x; acc[7] += v * a67.y;
}

// ---------------- SpMM1: 32 lanes x uint4 (16B) = 512B row, 4-wide unroll --------
__global__ void k_spmm1() {
    int r = blockIdx.x * 8 + threadIdx.y;
    if (r >= N_NODES) return;
    int f8 = threadIdx.x * 8;               // 32 lanes x 8 halves = 256
    int e   = g_rowptr[r];
    int end = g_rowptr[r + 1];
    float acc[8];
#pragma unroll
    for (int q = 0; q < 8; q++) acc[q] = 0.f;
    for (; e + 4 <= end; e += 4) {
        int2 cv0 = __ldg(&g_ecv[e]);
        int2 cv1 = __ldg(&g_ecv[e + 1]);
        int2 cv2 = __ldg(&g_ecv[e + 2]);
        int2 cv3 = __ldg(&g_ecv[e + 3]);
        uint4 x0 = __ldg((const uint4*)&g_H1[(size_t)cv0.x * D_HID + f8]);
        uint4 x1 = __ldg((const uint4*)&g_H1[(size_t)cv1.x * D_HID + f8]);
        uint4 x2 = __ldg((const uint4*)&g_H1[(size_t)cv2.x * D_HID + f8]);
        uint4 x3 = __ldg((const uint4*)&g_H1[(size_t)cv3.x * D_HID + f8]);
        fma_h8(acc, __int_as_float(cv0.y), x0);
        fma_h8(acc, __int_as_float(cv1.y), x1);
        fma_h8(acc, __int_as_float(cv2.y), x2);
        fma_h8(acc, __int_as_float(cv3.y), x3);
    }
    for (; e < end; e++) {
        int2 cv = __ldg(&g_ecv[e]);
        uint4 x = __ldg((const uint4*)&g_H1[(size_t)cv.x * D_HID + f8]);
        fma_h8(acc, __int_as_float(cv.y), x);
    }
    uint4 h;
    __half2 p0 = __floats2half2_rn(fmaxf(acc[0], 0.f), fmaxf(acc[1], 0.f));
    __half2 p1 = __floats2half2_rn(fmaxf(acc[2], 0.f), fmaxf(acc[3], 0.f));
    __half2 p2 = __floats2half2_rn(fmaxf(acc[4], 0.f), fmaxf(acc[5], 0.f));
    __half2 p3 = __floats2half2_rn(fmaxf(acc[6], 0.f), fmaxf(acc[7], 0.f));
    h.x = *(uint32_t*)&p0; h.y = *(uint32_t*)&p1;
    h.z = *(uint32_t*)&p2; h.w = *(uint32_t*)&p3;
    *(uint4*)&g_H2[(size_t)r * D_HID + f8] = h;
}

// ---------------- SpMM2: 16 lanes x uint4 (16B) = 256B row, 4-wide unroll --------
__global__ void k_spmm2(float* __restrict__ out) {
    int r = blockIdx.x * 16 + threadIdx.y;
    if (r >= N_NODES) return;
    int f8 = threadIdx.x * 8;               // 16 lanes x 8 halves = 128
    int e   = g_rowptr[r];
    int end = g_rowptr[r + 1];
    float acc[8];
#pragma unroll
    for (int q = 0; q < 8; q++) acc[q] = 0.f;
    for (; e + 4 <= end; e += 4) {
        int2 cv0 = __ldg(&g_ecv[e]);
        int2 cv1 = __ldg(&g_ecv[e + 1]);
        int2 cv2 = __ldg(&g_ecv[e + 2]);
        int2 cv3 = __ldg(&g_ecv[e + 3]);
        uint4 x0 = __ldg((const uint4*)&g_H3[(size_t)cv0.x * D_OUT + f8]);
        uint4 x1 = __ldg((const uint4*)&g_H3[(size_t)cv1.x * D_OUT + f8]);
        uint4 x2 = __ldg((const uint4*)&g_H3[(size_t)cv2.x * D_OUT + f8]);
        uint4 x3 = __ldg((const uint4*)&g_H3[(size_t)cv3.x * D_OUT + f8]);
        fma_h8(acc, __int_as_float(cv0.y), x0);
        fma_h8(acc, __int_as_float(cv1.y), x1);
        fma_h8(acc, __int_as_float(cv2.y), x2);
        fma_h8(acc, __int_as_float(cv3.y), x3);
    }
    for (; e < end; e++) {
        int2 cv = __ldg(&g_ecv[e]);
        uint4 x = __ldg((const uint4*)&g_H3[(size_t)cv.x * D_OUT + f8]);
        fma_h8(acc, __int_as_float(cv.y), x);
    }
    float* op = &out[(size_t)r * D_OUT + f8];
    *(float4*)op       = make_float4(acc[0], acc[1], acc[2], acc[3]);
    *(float4*)(op + 4) = make_float4(acc[4], acc[5], acc[6], acc[7]);
}

// ---------------- launch -----------------------------------------------------------
extern "C" void kernel_launch(void* const* d_in, const int* in_sizes, int n_in,
                              void* d_out, int out_size) {
    const float* Y        = (const float*)d_in[0];
    const int*   edge_row = (const int*)d_in[1];
    const int*   edge_col = (const int*)d_in[2];
    const float* edge_val = (const float*)d_in[3];
    const float* W1       = (const float*)d_in[4];
    const float* W2       = (const float*)d_in[5];
    float*       out      = (float*)d_out;

    int *pRowptr;
    cudaGetSymbolAddress((void**)&pRowptr, g_rowptr);

    cudaFuncSetAttribute(k_gemm1_scatter,
                         cudaFuncAttributeMaxDynamicSharedMemorySize, DSM1);
    cudaFuncSetAttribute(k_gemm2,
                         cudaFuncAttributeMaxDynamicSharedMemorySize, DSM2);

    cudaMemsetAsync(pRowptr, 0, (N_NODES + 1) * sizeof(int));
    k_init_all<<<HISTB + 256 + 128 + YSPB, 256>>>(edge_row, W1, W2, Y);
    k_scan1<<<196, 256>>>();
    k_scan3<<<196, 256>>>();
    k_gemm1_scatter<<<GGRID, 512, DSM1>>>(edge_row, edge_col, edge_val);
    {
        dim3 blk(32, 8);
        k_spmm1<<<(N_NODES + 7) / 8, blk>>>();
    }
    k_gemm2<<<GGRID, 512, DSM2>>>();
    {
        dim3 blk(16, 16);
        k_spmm2<<<(N_NODES + 15) / 16, blk>>>(out);
    }
}